// round 2
// baseline (speedup 1.0000x reference)
#include <cuda_runtime.h>
#include <cuda_bf16.h>
#include <math_constants.h>

// Problem constants
#define NPIX 2304          // 48*48
#define CIN  256
#define HID  128           // heads*dim_head
#define NHEADS 4
#define DHEAD 32
#define BATCH 8
#define QSCALE 0.17677669529663687f   // 1/sqrt(32)

// Scratch (allocation-free rule: __device__ globals)
__device__ float g_q[BATCH * HID * NPIX];   // [bh][d][n], q pre-scaled
__device__ float g_k[BATCH * HID * NPIX];   // [bh][d][n]
__device__ float g_v[BATCH * HID * NPIX];   // [bh][d][n]
__device__ float g_o[BATCH * HID * NPIX];   // [b][c][n], c = h*32+d

// ---------------------------------------------------------------------------
// Kernel 1: QKV projection.  C[384, 2304] = W[384,256] @ X_b[256,2304]
// Tiled GEMM BM=64 BN=64 BK=16, 256 threads, 4x4 per thread.
// Routes outputs into g_q (scaled), g_k, g_v in [bh][d][n] layout.
// ---------------------------------------------------------------------------
__global__ void qkv_kernel(const float* __restrict__ x,
                           const float* __restrict__ w)
{
    __shared__ float As[16][64];   // As[k][o]
    __shared__ float Bs[16][64];   // Bs[k][n]

    const int b  = blockIdx.z;
    const int ob = blockIdx.y * 64;
    const int nb = blockIdx.x * 64;
    const int tid = threadIdx.x;

    const float* xb = x + (size_t)b * CIN * NPIX;

    float acc[4][4] = {};
    const int to = (tid >> 4) << 2;   // 0..60
    const int tn = (tid & 15) << 2;   // 0..60

    for (int kb = 0; kb < CIN; kb += 16) {
        #pragma unroll
        for (int i = tid; i < 64 * 16; i += 256) {
            int o = i >> 4, k = i & 15;
            As[k][o] = w[(ob + o) * CIN + kb + k];
        }
        #pragma unroll
        for (int i = tid; i < 16 * 64; i += 256) {
            int k = i >> 6, n = i & 63;
            Bs[k][n] = xb[(size_t)(kb + k) * NPIX + nb + n];
        }
        __syncthreads();
        #pragma unroll
        for (int k = 0; k < 16; k++) {
            float4 a = *(const float4*)&As[k][to];
            float4 bb = *(const float4*)&Bs[k][tn];
            float av[4] = {a.x, a.y, a.z, a.w};
            float bv[4] = {bb.x, bb.y, bb.z, bb.w};
            #pragma unroll
            for (int i = 0; i < 4; i++)
                #pragma unroll
                for (int j = 0; j < 4; j++)
                    acc[i][j] = fmaf(av[i], bv[j], acc[i][j]);
        }
        __syncthreads();
    }

    #pragma unroll
    for (int i = 0; i < 4; i++) {
        int o   = ob + to + i;
        int sec = o >> 7;           // 0=q,1=k,2=v
        int oc  = o & 127;
        int bh  = b * NHEADS + (oc >> 5);
        int d   = oc & 31;
        float mult = (sec == 0) ? QSCALE : 1.0f;
        float4 val = make_float4(acc[i][0] * mult, acc[i][1] * mult,
                                 acc[i][2] * mult, acc[i][3] * mult);
        float* dst = (sec == 0) ? g_q : (sec == 1) ? g_k : g_v;
        *(float4*)&dst[((size_t)(bh * 32 + d)) * NPIX + nb + tn] = val;
    }
}

// ---------------------------------------------------------------------------
// Kernel 2: flash attention. One thread = one query. 128 queries/block.
// K/V tiles (32 keys x 32 dims) staged in smem, broadcast float4 reads.
// Online softmax fully per-thread (no cross-thread reductions needed).
// ---------------------------------------------------------------------------
__global__ void __launch_bounds__(128) attn_kernel()
{
    const int bh = blockIdx.y;
    const int qn = blockIdx.x * 128 + threadIdx.x;

    const float* qp = g_q + (size_t)bh * DHEAD * NPIX;
    const float* kp = g_k + (size_t)bh * DHEAD * NPIX;
    const float* vp = g_v + (size_t)bh * DHEAD * NPIX;

    float q[32];
    #pragma unroll
    for (int d = 0; d < 32; d++)
        q[d] = qp[(size_t)d * NPIX + qn];       // coalesced per d

    float acc[32] = {};
    float m = -CUDART_INF_F;
    float l = 0.0f;

    __shared__ float ks[32 * 32];   // [d][j] as float4-friendly flat array
    __shared__ float vs[32 * 32];

    for (int kb = 0; kb < NPIX; kb += 32) {
        __syncthreads();
        #pragma unroll
        for (int i = threadIdx.x; i < 32 * 8; i += 128) {  // 256 float4 per array
            int d = i >> 3, j4 = i & 7;
            const size_t src = (size_t)d * NPIX + kb + j4 * 4;
            ((float4*)ks)[i] = *(const float4*)&kp[src];
            ((float4*)vs)[i] = *(const float4*)&vp[src];
        }
        __syncthreads();

        float s[32];
        #pragma unroll
        for (int j4 = 0; j4 < 8; j4++) {
            float4 a4 = make_float4(0.f, 0.f, 0.f, 0.f);
            #pragma unroll
            for (int d = 0; d < 32; d++) {
                float4 kk = ((const float4*)ks)[d * 8 + j4];   // broadcast
                a4.x = fmaf(q[d], kk.x, a4.x);
                a4.y = fmaf(q[d], kk.y, a4.y);
                a4.z = fmaf(q[d], kk.z, a4.z);
                a4.w = fmaf(q[d], kk.w, a4.w);
            }
            s[4 * j4 + 0] = a4.x; s[4 * j4 + 1] = a4.y;
            s[4 * j4 + 2] = a4.z; s[4 * j4 + 3] = a4.w;
        }

        float mt = s[0];
        #pragma unroll
        for (int j = 1; j < 32; j++) mt = fmaxf(mt, s[j]);
        float mnew = fmaxf(m, mt);
        float alpha = __expf(m - mnew);          // first iter: exp(-inf)=0
        l *= alpha;
        #pragma unroll
        for (int d = 0; d < 32; d++) acc[d] *= alpha;
        #pragma unroll
        for (int j = 0; j < 32; j++) {
            s[j] = __expf(s[j] - mnew);
            l += s[j];
        }
        #pragma unroll
        for (int d = 0; d < 32; d++) {
            float a = acc[d];
            #pragma unroll
            for (int j4 = 0; j4 < 8; j4++) {
                float4 vv = ((const float4*)vs)[d * 8 + j4];   // broadcast
                a = fmaf(s[4 * j4 + 0], vv.x, a);
                a = fmaf(s[4 * j4 + 1], vv.y, a);
                a = fmaf(s[4 * j4 + 2], vv.z, a);
                a = fmaf(s[4 * j4 + 3], vv.w, a);
            }
            acc[d] = a;
        }
        m = mnew;
    }

    const float inv = 1.0f / l;
    float* op = g_o + (size_t)bh * DHEAD * NPIX;   // bh*32+d == b*128 + h*32+d
    #pragma unroll
    for (int d = 0; d < 32; d++)
        op[(size_t)d * NPIX + qn] = acc[d] * inv;   // coalesced per d
}

// ---------------------------------------------------------------------------
// Kernel 3: output projection + bias.
// C[256, 2304] = W_out[256,128] @ G_o[b][128, 2304] + b_out
// ---------------------------------------------------------------------------
__global__ void proj_kernel(const float* __restrict__ w,
                            const float* __restrict__ bias,
                            float* __restrict__ out)
{
    __shared__ float As[16][64];
    __shared__ float Bs[16][64];

    const int b  = blockIdx.z;
    const int ob = blockIdx.y * 64;
    const int nb = blockIdx.x * 64;
    const int tid = threadIdx.x;

    const float* gb = g_o + (size_t)b * HID * NPIX;

    float acc[4][4] = {};
    const int to = (tid >> 4) << 2;
    const int tn = (tid & 15) << 2;

    for (int kb = 0; kb < HID; kb += 16) {
        #pragma unroll
        for (int i = tid; i < 64 * 16; i += 256) {
            int o = i >> 4, k = i & 15;
            As[k][o] = w[(ob + o) * HID + kb + k];
        }
        #pragma unroll
        for (int i = tid; i < 16 * 64; i += 256) {
            int k = i >> 6, n = i & 63;
            Bs[k][n] = gb[(size_t)(kb + k) * NPIX + nb + n];
        }
        __syncthreads();
        #pragma unroll
        for (int k = 0; k < 16; k++) {
            float4 a = *(const float4*)&As[k][to];
            float4 bb = *(const float4*)&Bs[k][tn];
            float av[4] = {a.x, a.y, a.z, a.w};
            float bv[4] = {bb.x, bb.y, bb.z, bb.w};
            #pragma unroll
            for (int i = 0; i < 4; i++)
                #pragma unroll
                for (int j = 0; j < 4; j++)
                    acc[i][j] = fmaf(av[i], bv[j], acc[i][j]);
        }
        __syncthreads();
    }

    #pragma unroll
    for (int i = 0; i < 4; i++) {
        int o = ob + to + i;
        float bv = bias[o];
        float4 val = make_float4(acc[i][0] + bv, acc[i][1] + bv,
                                 acc[i][2] + bv, acc[i][3] + bv);
        *(float4*)&out[((size_t)(b * CIN + o)) * NPIX + nb + tn] = val;
    }
}

// ---------------------------------------------------------------------------
extern "C" void kernel_launch(void* const* d_in, const int* in_sizes, int n_in,
                              void* d_out, int out_size)
{
    const float* x     = (const float*)d_in[0];  // [8,256,48,48]
    const float* w_qkv = (const float*)d_in[1];  // [384,256]
    const float* w_out = (const float*)d_in[2];  // [256,128]
    const float* b_out = (const float*)d_in[3];  // [256]
    float* out = (float*)d_out;                  // [8,256,48,48]

    // Kernel 1: QKV projection
    {
        dim3 grid(NPIX / 64, (3 * HID) / 64, BATCH);   // 36 x 6 x 8
        qkv_kernel<<<grid, 256>>>(x, w_qkv);
    }
    // Kernel 2: attention
    {
        dim3 grid(NPIX / 128, BATCH * NHEADS);          // 18 x 32
        attn_kernel<<<grid, 128>>>();
    }
    // Kernel 3: output projection
    {
        dim3 grid(NPIX / 64, CIN / 64, BATCH);          // 36 x 4 x 8
        proj_kernel<<<grid, 256>>>(w_out, b_out, out);
    }
}